// round 2
// baseline (speedup 1.0000x reference)
#include <cuda_runtime.h>
#include <cuda_bf16.h>

#define MAXN 50000
#define MAXE 800000
#define HDIM 96
#define HDIM2 192

// ---------------- scratch (device globals; no allocation allowed) ----------------
__device__ int   g_deg_in[MAXN];
__device__ int   g_deg_out[MAXN];
__device__ int   g_fill[MAXN];
__device__ int   g_rowptr[MAXN + 1];
__device__ int   g_col[MAXE];
__device__ float g_norm_in[MAXN];
__device__ float g_norm_out[MAXN];
__device__ float g_Y[(size_t)MAXN * HDIM];    // x @ W1
__device__ float g_HB[(size_t)MAXN * HDIM2];  // dual-view features entering aggregation
__device__ float g_P[(size_t)MAXN * HDIM2];   // layer-1 post-PReLU
__device__ float g_wsum[HDIM];
__device__ float g_bmsum;

// ---------------- small setup kernels ----------------
__global__ void zero_kernel(int n) {
    int i = blockIdx.x * blockDim.x + threadIdx.x;
    if (i < n) { g_deg_in[i] = 0; g_deg_out[i] = 0; g_fill[i] = 0; }
}

__global__ void degree_kernel(const int* __restrict__ src, const int* __restrict__ dst, int e) {
    int i = blockIdx.x * blockDim.x + threadIdx.x;
    if (i < e) {
        atomicAdd(&g_deg_out[src[i]], 1);
        atomicAdd(&g_deg_in[dst[i]], 1);
    }
}

// Single-block exclusive scan of in-degrees -> rowptr; also norms + Wm row-sums.
__global__ void scan_kernel(int n, const float* __restrict__ Wm, const float* __restrict__ bm) {
    __shared__ int ssum[1024];
    int t = threadIdx.x;

    if (t < HDIM) {
        float s = 0.f;
        #pragma unroll 8
        for (int j = 0; j < HDIM; j++) s += Wm[t * HDIM + j];
        g_wsum[t] = s;
    }
    if (t == 0) {
        float s = 0.f;
        for (int j = 0; j < HDIM; j++) s += bm[j];
        g_bmsum = s;
    }

    int chunk = (n + 1023) / 1024;
    int beg = min(t * chunk, n);
    int end = min(beg + chunk, n);
    int s = 0;
    for (int i = beg; i < end; i++) s += g_deg_in[i];
    ssum[t] = s;
    __syncthreads();
    for (int off = 1; off < 1024; off <<= 1) {
        int v = (t >= off) ? ssum[t - off] : 0;
        __syncthreads();
        ssum[t] += v;
        __syncthreads();
    }
    int run = ssum[t] - s;  // exclusive prefix of this thread's chunk
    for (int i = beg; i < end; i++) { g_rowptr[i] = run; run += g_deg_in[i]; }
    if (end == n) g_rowptr[n] = run;

    for (int i = beg; i < end; i++) {
        g_norm_in[i]  = rsqrtf((float)max(g_deg_in[i], 1));
        g_norm_out[i] = rsqrtf((float)max(g_deg_out[i], 1));
    }
}

__global__ void fill_kernel(const int* __restrict__ src, const int* __restrict__ dst, int e) {
    int i = blockIdx.x * blockDim.x + threadIdx.x;
    if (i < e) {
        int d = dst[i];
        int pos = g_rowptr[d] + atomicAdd(&g_fill[d], 1);
        g_col[pos] = src[i];
    }
}

// ---------------- generic fp32 GEMM: C[m][0..95] = rowscale[m] * (A[m,:K] @ B[K,96]) ----------------
__global__ __launch_bounds__(256) void gemm96_kernel(
    const float* __restrict__ A, int lda,
    const float* __restrict__ B,
    float* __restrict__ C, int ldc,
    const float* __restrict__ rowscale,
    int M, int K)
{
    __shared__ float As[16][65];   // padded, transposed A tile
    __shared__ float Bs[16][96];
    int tid = threadIdx.x;
    int tx = tid & 15;   // 16 col-groups x 6 cols
    int ty = tid >> 4;   // 16 row-groups x 4 rows
    int row0 = blockIdx.x * 64;

    float acc[4][6];
    #pragma unroll
    for (int r = 0; r < 4; r++)
        #pragma unroll
        for (int c = 0; c < 6; c++) acc[r][c] = 0.f;

    for (int k0 = 0; k0 < K; k0 += 16) {
        #pragma unroll
        for (int idx = tid; idx < 64 * 16; idx += 256) {
            int m = idx >> 4, kk = idx & 15;
            int gr = row0 + m, gk = k0 + kk;
            As[kk][m] = (gr < M && gk < K) ? A[(size_t)gr * lda + gk] : 0.f;
        }
        #pragma unroll
        for (int idx = tid; idx < 16 * 96; idx += 256) {
            int kk = idx / 96, c = idx - kk * 96;
            int gk = k0 + kk;
            Bs[kk][c] = (gk < K) ? B[gk * HDIM + c] : 0.f;
        }
        __syncthreads();
        #pragma unroll
        for (int kk = 0; kk < 16; kk++) {
            float a[4], b[6];
            #pragma unroll
            for (int r = 0; r < 4; r++) a[r] = As[kk][ty * 4 + r];
            #pragma unroll
            for (int c = 0; c < 6; c++) b[c] = Bs[kk][tx * 6 + c];
            #pragma unroll
            for (int r = 0; r < 4; r++)
                #pragma unroll
                for (int c = 0; c < 6; c++) acc[r][c] = fmaf(a[r], b[c], acc[r][c]);
        }
        __syncthreads();
    }

    #pragma unroll
    for (int r = 0; r < 4; r++) {
        int m = row0 + ty * 4 + r;
        if (m < M) {
            float sc = rowscale ? rowscale[m] : 1.f;
            #pragma unroll
            for (int c = 0; c < 6; c++)
                C[(size_t)m * ldc + tx * 6 + c] = acc[r][c] * sc;
        }
    }
}

// HB[i][0:96] = norm_out[i]*Y[i];  HB[i][96:192] = norm_out[i]*Y[perm[i]]
__global__ void build_hb_kernel(const int* __restrict__ perm, int n) {
    int i = blockIdx.x * blockDim.x + threadIdx.x;
    if (i < n * HDIM) {
        int node = i / HDIM, c = i - node * HDIM;
        float no = g_norm_out[node];
        g_HB[(size_t)node * HDIM2 + c]        = no * g_Y[(size_t)node * HDIM + c];
        g_HB[(size_t)node * HDIM2 + HDIM + c] = no * g_Y[(size_t)perm[node] * HDIM + c];
    }
}

// ---------------- gather-aggregation (one warp per node, both views) ----------------
// mode final=0: Pout[node][ch] = prelu(agg*norm_in + b, a)
// mode final=1: out[node] / out[n+node] = z . wsum + bmsum   (per view)
__global__ __launch_bounds__(256) void spmm_kernel(
    const float* __restrict__ Hin, float* __restrict__ Pout,
    const float* __restrict__ b, const float* __restrict__ a,
    float* __restrict__ out, int n, int final)
{
    int gw = (blockIdx.x * blockDim.x + threadIdx.x) >> 5;
    int lane = threadIdx.x & 31;
    if (gw >= n) return;

    int beg = g_rowptr[gw], end = g_rowptr[gw + 1];
    float2 acc0 = {0.f, 0.f}, acc1 = {0.f, 0.f}, acc2 = {0.f, 0.f};

    int e = beg;
    for (; e + 1 < end; e += 2) {   // 2-edge unroll for MLP
        int s0 = g_col[e], s1 = g_col[e + 1];
        const float2* h0 = (const float2*)(Hin + (size_t)s0 * HDIM2);
        const float2* h1 = (const float2*)(Hin + (size_t)s1 * HDIM2);
        float2 u0 = h0[lane], u1 = h0[lane + 32], u2 = h0[lane + 64];
        float2 v0 = h1[lane], v1 = h1[lane + 32], v2 = h1[lane + 64];
        acc0.x += u0.x + v0.x; acc0.y += u0.y + v0.y;
        acc1.x += u1.x + v1.x; acc1.y += u1.y + v1.y;
        acc2.x += u2.x + v2.x; acc2.y += u2.y + v2.y;
    }
    if (e < end) {
        int s0 = g_col[e];
        const float2* h0 = (const float2*)(Hin + (size_t)s0 * HDIM2);
        float2 u0 = h0[lane], u1 = h0[lane + 32], u2 = h0[lane + 64];
        acc0.x += u0.x; acc0.y += u0.y;
        acc1.x += u1.x; acc1.y += u1.y;
        acc2.x += u2.x; acc2.y += u2.y;
    }

    float ni = g_norm_in[gw];
    float s1 = 0.f, s2 = 0.f;
    float2* po = Pout ? (float2*)(Pout + (size_t)gw * HDIM2) : nullptr;

    #pragma unroll
    for (int j = 0; j < 3; j++) {
        int idx = lane + 32 * j;
        float2 acc = (j == 0) ? acc0 : (j == 1) ? acc1 : acc2;
        int v = idx >= 48;            // view of this float2 (96 channels per view, even split)
        int c0 = 2 * idx - 96 * v;    // channel within view
        float h0 = acc.x * ni + b[c0];
        float h1 = acc.y * ni + b[c0 + 1];
        float z0 = (h0 >= 0.f) ? h0 : a[c0] * h0;
        float z1 = (h1 >= 0.f) ? h1 : a[c0 + 1] * h1;
        if (final) {
            float contrib = z0 * g_wsum[c0] + z1 * g_wsum[c0 + 1];
            if (v) s2 += contrib; else s1 += contrib;
        } else {
            po[idx] = make_float2(z0, z1);
        }
    }

    if (final) {
        #pragma unroll
        for (int off = 16; off > 0; off >>= 1) {
            s1 += __shfl_xor_sync(0xffffffff, s1, off);
            s2 += __shfl_xor_sync(0xffffffff, s2, off);
        }
        if (lane == 0) {
            out[gw]     = s1 + g_bmsum;
            out[n + gw] = s2 + g_bmsum;
        }
    }
}

// ---------------- launch ----------------
extern "C" void kernel_launch(void* const* d_in, const int* in_sizes, int n_in,
                              void* d_out, int out_size) {
    const float* x   = (const float*)d_in[0];
    const int*   src = (const int*)  d_in[1];
    const int*   dst = (const int*)  d_in[2];
    const int*   perm= (const int*)  d_in[3];
    const float* W1  = (const float*)d_in[4];
    const float* b1  = (const float*)d_in[5];
    const float* a1  = (const float*)d_in[6];
    const float* W2  = (const float*)d_in[7];
    const float* b2  = (const float*)d_in[8];
    const float* a2  = (const float*)d_in[9];
    const float* Wm  = (const float*)d_in[10];
    const float* bm  = (const float*)d_in[11];
    float* out = (float*)d_out;

    int E = in_sizes[1];
    int n = in_sizes[3];
    int F = in_sizes[0] / n;

    float *pY, *pHB, *pP, *pNormOut;
    cudaGetSymbolAddress((void**)&pY, g_Y);
    cudaGetSymbolAddress((void**)&pHB, g_HB);
    cudaGetSymbolAddress((void**)&pP, g_P);
    cudaGetSymbolAddress((void**)&pNormOut, g_norm_out);

    zero_kernel<<<(n + 255) / 256, 256>>>(n);
    degree_kernel<<<(E + 255) / 256, 256>>>(src, dst, E);
    scan_kernel<<<1, 1024>>>(n, Wm, bm);
    fill_kernel<<<(E + 255) / 256, 256>>>(src, dst, E);

    // Y = X @ W1  (shared by both views)
    gemm96_kernel<<<(n + 63) / 64, 256>>>(x, F, W1, pY, HDIM, nullptr, n, F);
    // dual-view scaled features
    build_hb_kernel<<<((size_t)n * HDIM + 255) / 256, 256>>>(perm, n);
    // layer-1 aggregation + PReLU
    spmm_kernel<<<(n + 7) / 8, 256>>>(pHB, pP, b1, a1, nullptr, n, 0);
    // layer-2 GEMMs (shared W2), norm_out fused in epilogue
    gemm96_kernel<<<(n + 63) / 64, 256>>>(pP,        HDIM2, W2, pHB,        HDIM2, pNormOut, n, HDIM);
    gemm96_kernel<<<(n + 63) / 64, 256>>>(pP + HDIM, HDIM2, W2, pHB + HDIM, HDIM2, pNormOut, n, HDIM);
    // layer-2 aggregation + PReLU + fused projection row-sum
    spmm_kernel<<<(n + 7) / 8, 256>>>(pHB, nullptr, b2, a2, out, n, 1);
}

// round 3
// speedup vs baseline: 1.0436x; 1.0436x over previous
#include <cuda_runtime.h>
#include <cuda_bf16.h>

#define MAXN 50000
#define MAXE 800000
#define HDIM 96
#define HDIM2 192

// ---------------- scratch (device globals; no allocation allowed) ----------------
__device__ int   g_deg_in[MAXN];
__device__ int   g_deg_out[MAXN];
__device__ int   g_fill[MAXN];
__device__ int   g_rowptr[MAXN + 1];
__device__ int   g_col[MAXE];
__device__ float g_norm_in[MAXN];
__device__ float g_norm_out[MAXN];
__device__ float g_Y[(size_t)MAXN * HDIM];    // x @ W1
__device__ float g_HB[(size_t)MAXN * HDIM2];  // dual-view features entering aggregation
__device__ float g_P[(size_t)MAXN * HDIM2];   // layer-1 post-PReLU
__device__ float g_wsum[HDIM];
__device__ float g_bmsum;

// packed f32x2 FMA: acc = a * b + acc  (two fp32 lanes per 64-bit reg)
__device__ __forceinline__ void fma_f32x2(unsigned long long& acc,
                                          unsigned long long a,
                                          unsigned long long b) {
    asm("fma.rn.f32x2 %0, %1, %2, %0;" : "+l"(acc) : "l"(a), "l"(b));
}

// ---------------- small setup kernels ----------------
__global__ void zero_kernel(int n) {
    int i = blockIdx.x * blockDim.x + threadIdx.x;
    if (i < n) { g_deg_in[i] = 0; g_deg_out[i] = 0; g_fill[i] = 0; }
}

__global__ void degree_kernel(const int* __restrict__ src, const int* __restrict__ dst, int e) {
    int i = blockIdx.x * blockDim.x + threadIdx.x;
    if (i < e) {
        atomicAdd(&g_deg_out[src[i]], 1);
        atomicAdd(&g_deg_in[dst[i]], 1);
    }
}

// Single-block exclusive scan of in-degrees -> rowptr; also norms + Wm row-sums.
__global__ void scan_kernel(int n, const float* __restrict__ Wm, const float* __restrict__ bm) {
    __shared__ int ssum[1024];
    int t = threadIdx.x;

    if (t < HDIM) {
        float s = 0.f;
        #pragma unroll 8
        for (int j = 0; j < HDIM; j++) s += Wm[t * HDIM + j];
        g_wsum[t] = s;
    }
    if (t == 0) {
        float s = 0.f;
        for (int j = 0; j < HDIM; j++) s += bm[j];
        g_bmsum = s;
    }

    int chunk = (n + 1023) / 1024;
    int beg = min(t * chunk, n);
    int end = min(beg + chunk, n);
    int s = 0;
    for (int i = beg; i < end; i++) s += g_deg_in[i];
    ssum[t] = s;
    __syncthreads();
    for (int off = 1; off < 1024; off <<= 1) {
        int v = (t >= off) ? ssum[t - off] : 0;
        __syncthreads();
        ssum[t] += v;
        __syncthreads();
    }
    int run = ssum[t] - s;  // exclusive prefix of this thread's chunk
    for (int i = beg; i < end; i++) { g_rowptr[i] = run; run += g_deg_in[i]; }
    if (end == n) g_rowptr[n] = run;

    for (int i = beg; i < end; i++) {
        g_norm_in[i]  = rsqrtf((float)max(g_deg_in[i], 1));
        g_norm_out[i] = rsqrtf((float)max(g_deg_out[i], 1));
    }
}

__global__ void fill_kernel(const int* __restrict__ src, const int* __restrict__ dst, int e) {
    int i = blockIdx.x * blockDim.x + threadIdx.x;
    if (i < e) {
        int d = dst[i];
        int pos = g_rowptr[d] + atomicAdd(&g_fill[d], 1);
        g_col[pos] = src[i];
    }
}

// ---------------- f32x2 GEMM: C[m][0..95] = rowscale[m] * (A[m,:K] @ B[K,96]) ----------
// 128x96 tile, 256 threads, 8 rows x 6 cols per thread.
// Accumulators packed over ROW PAIRS (A tile k-major, rows contiguous -> LDS.64 gives pair).
// B tile pre-duplicated (b,b) in smem so broadcast operand is one LDS.64.
__global__ __launch_bounds__(256) void gemm96_kernel(
    const float* __restrict__ A, int lda,
    const float* __restrict__ B,
    float* __restrict__ C, int ldc,
    const float* __restrict__ rowscale,
    int M, int K)
{
    __shared__ __align__(16) float As[16][132];          // [kk][m], padded
    __shared__ unsigned long long Bs2[16][96];           // [kk][c] -> (b,b)
    int tid = threadIdx.x;
    int tx = tid & 15;   // col group: cols tx + 16*c
    int ty = tid >> 4;   // row group: rows ty*8 .. ty*8+7
    int row0 = blockIdx.x * 128;

    unsigned long long acc[4][6];
    #pragma unroll
    for (int r = 0; r < 4; r++)
        #pragma unroll
        for (int c = 0; c < 6; c++) acc[r][c] = 0ull;

    for (int k0 = 0; k0 < K; k0 += 16) {
        // A tile: 128 rows x 16 k, global loads k-contiguous per thread group
        #pragma unroll
        for (int i = 0; i < 8; i++) {
            int idx = tid + i * 256;      // 0..2047
            int m = idx >> 4, kk = idx & 15;
            int gr = row0 + m, gk = k0 + kk;
            As[kk][m] = (gr < M && gk < K) ? A[(size_t)gr * lda + gk] : 0.f;
        }
        // B tile, duplicated into both 32-bit halves
        #pragma unroll
        for (int i = 0; i < 6; i++) {
            int idx = tid + i * 256;      // 0..1535
            int kk = idx / 96, c = idx - kk * 96;
            int gk = k0 + kk;
            float bv = (gk < K) ? B[gk * HDIM + c] : 0.f;
            unsigned int u = __float_as_uint(bv);
            Bs2[kk][c] = ((unsigned long long)u << 32) | u;
        }
        __syncthreads();
        #pragma unroll
        for (int kk = 0; kk < 16; kk++) {
            unsigned long long ap[4], bp[6];
            #pragma unroll
            for (int r = 0; r < 4; r++)
                ap[r] = *(const unsigned long long*)&As[kk][ty * 8 + 2 * r];
            #pragma unroll
            for (int c = 0; c < 6; c++)
                bp[c] = Bs2[kk][tx + 16 * c];
            #pragma unroll
            for (int r = 0; r < 4; r++)
                #pragma unroll
                for (int c = 0; c < 6; c++)
                    fma_f32x2(acc[r][c], ap[r], bp[c]);
        }
        __syncthreads();
    }

    #pragma unroll
    for (int r = 0; r < 4; r++) {
        int m0 = row0 + ty * 8 + 2 * r;
        #pragma unroll
        for (int h = 0; h < 2; h++) {
            int m = m0 + h;
            if (m < M) {
                float sc = rowscale ? rowscale[m] : 1.f;
                #pragma unroll
                for (int c = 0; c < 6; c++) {
                    unsigned int u = (unsigned int)(h ? (acc[r][c] >> 32)
                                                      : (acc[r][c] & 0xffffffffull));
                    C[(size_t)m * ldc + tx + 16 * c] = __uint_as_float(u) * sc;
                }
            }
        }
    }
}

// HB[i][0:96] = norm_out[i]*Y[i];  HB[i][96:192] = norm_out[i]*Y[perm[i]]
__global__ void build_hb_kernel(const int* __restrict__ perm, int n) {
    int i = blockIdx.x * blockDim.x + threadIdx.x;
    if (i < n * HDIM) {
        int node = i / HDIM, c = i - node * HDIM;
        float no = g_norm_out[node];
        g_HB[(size_t)node * HDIM2 + c]        = no * g_Y[(size_t)node * HDIM + c];
        g_HB[(size_t)node * HDIM2 + HDIM + c] = no * g_Y[(size_t)perm[node] * HDIM + c];
    }
}

// ---------------- gather-aggregation (one warp per node, both views) ----------------
__global__ __launch_bounds__(256) void spmm_kernel(
    const float* __restrict__ Hin, float* __restrict__ Pout,
    const float* __restrict__ b, const float* __restrict__ a,
    float* __restrict__ out, int n, int final)
{
    int gw = (blockIdx.x * blockDim.x + threadIdx.x) >> 5;
    int lane = threadIdx.x & 31;
    if (gw >= n) return;

    int beg = g_rowptr[gw], end = g_rowptr[gw + 1];
    float2 acc0 = {0.f, 0.f}, acc1 = {0.f, 0.f}, acc2 = {0.f, 0.f};

    int e = beg;
    for (; e + 1 < end; e += 2) {   // 2-edge unroll for MLP
        int s0 = g_col[e], s1 = g_col[e + 1];
        const float2* h0 = (const float2*)(Hin + (size_t)s0 * HDIM2);
        const float2* h1 = (const float2*)(Hin + (size_t)s1 * HDIM2);
        float2 u0 = h0[lane], u1 = h0[lane + 32], u2 = h0[lane + 64];
        float2 v0 = h1[lane], v1 = h1[lane + 32], v2 = h1[lane + 64];
        acc0.x += u0.x + v0.x; acc0.y += u0.y + v0.y;
        acc1.x += u1.x + v1.x; acc1.y += u1.y + v1.y;
        acc2.x += u2.x + v2.x; acc2.y += u2.y + v2.y;
    }
    if (e < end) {
        int s0 = g_col[e];
        const float2* h0 = (const float2*)(Hin + (size_t)s0 * HDIM2);
        float2 u0 = h0[lane], u1 = h0[lane + 32], u2 = h0[lane + 64];
        acc0.x += u0.x; acc0.y += u0.y;
        acc1.x += u1.x; acc1.y += u1.y;
        acc2.x += u2.x; acc2.y += u2.y;
    }

    float ni = g_norm_in[gw];
    float s1 = 0.f, s2 = 0.f;
    float2* po = Pout ? (float2*)(Pout + (size_t)gw * HDIM2) : nullptr;

    #pragma unroll
    for (int j = 0; j < 3; j++) {
        int idx = lane + 32 * j;
        float2 acc = (j == 0) ? acc0 : (j == 1) ? acc1 : acc2;
        int v = idx >= 48;            // view of this float2
        int c0 = 2 * idx - 96 * v;    // channel within view
        float h0 = acc.x * ni + b[c0];
        float h1 = acc.y * ni + b[c0 + 1];
        float z0 = (h0 >= 0.f) ? h0 : a[c0] * h0;
        float z1 = (h1 >= 0.f) ? h1 : a[c0 + 1] * h1;
        if (final) {
            float contrib = z0 * g_wsum[c0] + z1 * g_wsum[c0 + 1];
            if (v) s2 += contrib; else s1 += contrib;
        } else {
            po[idx] = make_float2(z0, z1);
        }
    }

    if (final) {
        #pragma unroll
        for (int off = 16; off > 0; off >>= 1) {
            s1 += __shfl_xor_sync(0xffffffff, s1, off);
            s2 += __shfl_xor_sync(0xffffffff, s2, off);
        }
        if (lane == 0) {
            out[gw]     = s1 + g_bmsum;
            out[n + gw] = s2 + g_bmsum;
        }
    }
}

// ---------------- launch ----------------
extern "C" void kernel_launch(void* const* d_in, const int* in_sizes, int n_in,
                              void* d_out, int out_size) {
    const float* x   = (const float*)d_in[0];
    const int*   src = (const int*)  d_in[1];
    const int*   dst = (const int*)  d_in[2];
    const int*   perm= (const int*)  d_in[3];
    const float* W1  = (const float*)d_in[4];
    const float* b1  = (const float*)d_in[5];
    const float* a1  = (const float*)d_in[6];
    const float* W2  = (const float*)d_in[7];
    const float* b2  = (const float*)d_in[8];
    const float* a2  = (const float*)d_in[9];
    const float* Wm  = (const float*)d_in[10];
    const float* bm  = (const float*)d_in[11];
    float* out = (float*)d_out;

    int E = in_sizes[1];
    int n = in_sizes[3];
    int F = in_sizes[0] / n;

    float *pY, *pHB, *pP, *pNormOut;
    cudaGetSymbolAddress((void**)&pY, g_Y);
    cudaGetSymbolAddress((void**)&pHB, g_HB);
    cudaGetSymbolAddress((void**)&pP, g_P);
    cudaGetSymbolAddress((void**)&pNormOut, g_norm_out);

    zero_kernel<<<(n + 255) / 256, 256>>>(n);
    degree_kernel<<<(E + 255) / 256, 256>>>(src, dst, E);
    scan_kernel<<<1, 1024>>>(n, Wm, bm);
    fill_kernel<<<(E + 255) / 256, 256>>>(src, dst, E);

    // Y = X @ W1  (shared by both views)
    gemm96_kernel<<<(n + 127) / 128, 256>>>(x, F, W1, pY, HDIM, nullptr, n, F);
    // dual-view scaled features
    build_hb_kernel<<<((size_t)n * HDIM + 255) / 256, 256>>>(perm, n);
    // layer-1 aggregation + PReLU
    spmm_kernel<<<(n + 7) / 8, 256>>>(pHB, pP, b1, a1, nullptr, n, 0);
    // layer-2 GEMMs (shared W2), norm_out fused in epilogue
    gemm96_kernel<<<(n + 127) / 128, 256>>>(pP,        HDIM2, W2, pHB,        HDIM2, pNormOut, n, HDIM);
    gemm96_kernel<<<(n + 127) / 128, 256>>>(pP + HDIM, HDIM2, W2, pHB + HDIM, HDIM2, pNormOut, n, HDIM);
    // layer-2 aggregation + PReLU + fused projection row-sum
    spmm_kernel<<<(n + 7) / 8, 256>>>(pHB, nullptr, b2, a2, out, n, 1);
}